// round 10
// baseline (speedup 1.0000x reference)
#include <cuda_runtime.h>
#include <cub/cub.cuh>
#include <cstdint>
#include <math.h>

// ---------------- problem constants ----------------
#define NBATCH 4
#define FH 50
#define FW 50
#define NA 22500          // anchors per batch (50*50*9)
#define NPRE 3000
#define NPOST 300
#define NWORDS 94         // ceil(3000/32)

// output layout (flattened tuple, float32)
#define OFF_LOCS   0            // 4*22500*4 = 360000
#define OFF_SCORES 360000       // 4*22500*2 = 180000
#define OFF_ROIS   540000       // 4*300*4   = 4800
#define OFF_RIDX   544800       // 1200
#define OFF_ANCH   546000       // 22500*4   = 90000

// ---------------- device scratch ----------------
__device__ float g_feat[(size_t)NBATCH * 2500 * 512];   // NHWC feat
__device__ float g_wT[(size_t)512 * 9 * 512];            // [ci][tap][ko]
__device__ float g_hwT[(size_t)512 * 54];                // [k][c]
__device__ float g_boxes[(size_t)NBATCH * NA * 4];
__device__ unsigned g_keys32[(size_t)NBATCH * NA];
__device__ unsigned g_keysOut32[(size_t)NBATCH * NA];
__device__ int g_vals[(size_t)NBATCH * NA];
__device__ int g_valsOut[(size_t)NBATCH * NA];
__device__ float g_top[(size_t)NBATCH * NPRE * 4];
__device__ unsigned char g_topValid[(size_t)NBATCH * NPRE];
__device__ unsigned g_nmsMask[(size_t)NBATCH * NPRE * NWORDS];
__device__ float g_abase[9][4];
__device__ unsigned char g_cubTemp[16 << 20];

// packed fp32x2 FMA: d.lo = a.lo*b.lo+d.lo ; d.hi = a.hi*b.hi+d.hi (exact fp32)
#define FMA2(d, a, w) \
    asm("fma.rn.f32x2 %0, %1, %2, %3;" : "=l"(d) : "l"(a), "l"(w), "l"(d))

// ---------------- anchor base table (double math, once) ----------------
__global__ void anchor_init() {
    int a = threadIdx.x;
    if (a >= 9) return;
    int ri = a / 3, si = a % 3;
    double rr = (ri == 0) ? 0.5 : ((ri == 1) ? 1.0 : 2.0);
    double ss = (si == 0) ? 8.0 : ((si == 1) ? 16.0 : 32.0);
    double hh = 16.0 * ss * sqrt(rr);
    double wwd = 16.0 * ss * sqrt(1.0 / rr);
    g_abase[a][0] = (float)(8.0 - wwd * 0.5);
    g_abase[a][1] = (float)(8.0 - hh * 0.5);
    g_abase[a][2] = (float)(8.0 + wwd * 0.5);
    g_abase[a][3] = (float)(8.0 + hh * 0.5);
}

// ---------------- weight transposes ----------------
__global__ void wtrans_kernel(const float* __restrict__ w) {
    int t = blockIdx.x * blockDim.x + threadIdx.x;
    if (t >= 512 * 9 * 512) return;
    int ko = t % 512;
    int tap = (t / 512) % 9;
    int ci = t / (512 * 9);
    g_wT[t] = w[((size_t)ko * 512 + ci) * 9 + tap];
}

__global__ void hwtrans_kernel(const float* __restrict__ loc_w,
                               const float* __restrict__ score_w) {
    int t = blockIdx.x * blockDim.x + threadIdx.x;
    if (t >= 512 * 54) return;
    int k = t / 54, c = t % 54;
    float v;
    if (c < 36) v = loc_w[(size_t)c * 512 + k];
    else        v = score_w[(size_t)(c - 36) * 512 + k];
    g_hwT[t] = v;
}

// ---------------- 3x3 conv + ReLU, f32x2 implicit GEMM v5 ----------------
// Block: 64 spatial x 256 ko, 256 threads = 8 warps.
// warp w -> ko group [nt*256 + w*32, +32): weights are BROADCAST LDS.128.
// lane l -> 2 spatial positions (mt*64 + 2l, +1): a-loads from dup-pair tile.
// Thread: 2 sp x 16 ko-pairs (u64 acc, FMA2 packs ko pairs).
#define CONV_SIN   (8 * 5 * 52)                      // dup pairs: 2080
#define CONV_SW    (8 * 9 * 256)                     // 18432 floats
#define CONV_SMEM  (CONV_SIN * 8 + CONV_SW * 4)      // 90368 B

__global__ void __launch_bounds__(256, 2) conv3x3_v5(const float* __restrict__ x,
                                                     const float* __restrict__ bias) {
    extern __shared__ unsigned char smraw[];
    float2* sIn2 = reinterpret_cast<float2*>(smraw);            // dup pairs
    float* sW = reinterpret_cast<float*>(smraw + CONV_SIN * 8);

    int mt = blockIdx.x;             // 0..39
    int nt = blockIdx.y;             // 0..1
    int n = blockIdx.z;              // 0..3
    int s0 = mt * 64;
    int y0 = s0 / 50;
    int tid = threadIdx.x;
    int wid = tid >> 5, lane = tid & 31;
    int koW = nt * 256 + wid * 32;   // this warp's 32 output channels

    int sp0 = s0 + 2 * lane;
    int sp1 = sp0 + 1;
    int sc0 = sp0 < 2499 ? sp0 : 2499;
    int sc1 = sp1 < 2499 ? sp1 : 2499;
    int off0 = (sc0 / 50 - y0 + 1) * 52 + (sc0 % 50) + 1;
    int off1 = (sc1 / 50 - y0 + 1) * 52 + (sc1 % 50) + 1;

    unsigned long long acc0[16], acc1[16];
#pragma unroll
    for (int k = 0; k < 16; k++) { acc0[k] = 0ull; acc1[k] = 0ull; }

    const unsigned long long* aBase =
        reinterpret_cast<const unsigned long long*>(sIn2);

    for (int c0 = 0; c0 < 512; c0 += 8) {
        __syncthreads();
        // input tile (duplicated pairs): rows y0-1..y0+3, cols -1..50
        for (int t = tid; t < CONV_SIN; t += 256) {
            int ci = t / 260;
            int rem = t % 260;
            int r = rem / 52;
            int cc = rem % 52;
            int gy = y0 - 1 + r;
            int gx = cc - 1;
            float v = 0.f;
            if (gy >= 0 && gy < FH && gx >= 0 && gx < FW)
                v = x[(((size_t)n * 512 + c0 + ci) * FH + gy) * FW + gx];
            sIn2[t] = make_float2(v, v);
        }
        // weights for this ci-chunk, all 9 taps (256 ko of this nt)
        for (int t = tid; t < CONV_SW; t += 256) {
            int ko = t & 255;
            int rest = t >> 8;
            int tap = rest % 9;
            int ci = rest / 9;
            sW[t] = g_wT[((size_t)(c0 + ci) * 9 + tap) * 512 + nt * 256 + ko];
        }
        __syncthreads();

#pragma unroll 1
        for (int ci = 0; ci < 8; ci++) {
            const unsigned long long* p0 = aBase + ci * 260 + off0;
            const unsigned long long* p1 = aBase + ci * 260 + off1;
            const float* wci = sW + ci * 9 * 256 + wid * 32;
#pragma unroll
            for (int dy = 0; dy < 3; dy++) {
#pragma unroll
                for (int dx = 0; dx < 3; dx++) {
                    const int tap = dy * 3 + dx;
                    const int d = (dy - 1) * 52 + (dx - 1);
                    unsigned long long av0 = p0[d];
                    unsigned long long av1 = p1[d];
                    const ulonglong2* wp =
                        reinterpret_cast<const ulonglong2*>(wci + tap * 256);
                    // first 8 ko-pairs
                    {
                        ulonglong2 w0 = wp[0], w1 = wp[1], w2 = wp[2], w3 = wp[3];
                        FMA2(acc0[0], av0, w0.x); FMA2(acc1[0], av1, w0.x);
                        FMA2(acc0[1], av0, w0.y); FMA2(acc1[1], av1, w0.y);
                        FMA2(acc0[2], av0, w1.x); FMA2(acc1[2], av1, w1.x);
                        FMA2(acc0[3], av0, w1.y); FMA2(acc1[3], av1, w1.y);
                        FMA2(acc0[4], av0, w2.x); FMA2(acc1[4], av1, w2.x);
                        FMA2(acc0[5], av0, w2.y); FMA2(acc1[5], av1, w2.y);
                        FMA2(acc0[6], av0, w3.x); FMA2(acc1[6], av1, w3.x);
                        FMA2(acc0[7], av0, w3.y); FMA2(acc1[7], av1, w3.y);
                    }
                    // second 8 ko-pairs
                    {
                        ulonglong2 w4 = wp[4], w5 = wp[5], w6 = wp[6], w7 = wp[7];
                        FMA2(acc0[8],  av0, w4.x); FMA2(acc1[8],  av1, w4.x);
                        FMA2(acc0[9],  av0, w4.y); FMA2(acc1[9],  av1, w4.y);
                        FMA2(acc0[10], av0, w5.x); FMA2(acc1[10], av1, w5.x);
                        FMA2(acc0[11], av0, w5.y); FMA2(acc1[11], av1, w5.y);
                        FMA2(acc0[12], av0, w6.x); FMA2(acc1[12], av1, w6.x);
                        FMA2(acc0[13], av0, w6.y); FMA2(acc1[13], av1, w6.y);
                        FMA2(acc0[14], av0, w7.x); FMA2(acc1[14], av1, w7.x);
                        FMA2(acc0[15], av0, w7.y); FMA2(acc1[15], av1, w7.y);
                    }
                }
            }
        }
    }

    // epilogue: + bias, ReLU, store NHWC (32 consecutive ko per thread)
#pragma unroll
    for (int s = 0; s < 2; s++) {
        int sp = s ? sp1 : sp0;
        if (sp < 2500) {
            const unsigned long long* ac = s ? acc1 : acc0;
            float* op = &g_feat[((size_t)n * 2500 + sp) * 512 + koW];
#pragma unroll
            for (int q = 0; q < 8; q++) {
                float4 bq = *reinterpret_cast<const float4*>(&bias[koW + 4 * q]);
                float2 pa = *reinterpret_cast<const float2*>(&ac[2 * q]);
                float2 pb = *reinterpret_cast<const float2*>(&ac[2 * q + 1]);
                float4 v;
                v.x = fmaxf(pa.x + bq.x, 0.f);
                v.y = fmaxf(pa.y + bq.y, 0.f);
                v.z = fmaxf(pb.x + bq.z, 0.f);
                v.w = fmaxf(pb.y + bq.w, 0.f);
                *reinterpret_cast<float4*>(op + 4 * q) = v;
            }
        }
    }
}

// ---------------- 1x1 heads (loc 36 + score 18) ----------------
__device__ __forceinline__ void write_head(float* out, int m, int c, float acc,
                                           const float* __restrict__ loc_b,
                                           const float* __restrict__ score_b) {
    int n = m / 2500, pos = m % 2500;
    if (c < 36) {
        int a = c >> 2, j = c & 3;
        out[(size_t)OFF_LOCS + ((size_t)n * NA + (size_t)pos * 9 + a) * 4 + j] = acc + loc_b[c];
    } else {
        int cc = c - 36;
        int a = cc >> 1, j = cc & 1;
        out[(size_t)OFF_SCORES + ((size_t)n * NA + (size_t)pos * 9 + a) * 2 + j] = acc + score_b[cc];
    }
}

__global__ void __launch_bounds__(256) heads_kernel(const float* __restrict__ loc_b,
                                                    const float* __restrict__ score_b,
                                                    float* out) {
    __shared__ float sf[16][512];
    int m0 = blockIdx.x * 16;
    int tid = threadIdx.x;
    for (int t = tid; t < 16 * 512; t += 256)
        sf[t >> 9][t & 511] = g_feat[((size_t)m0 << 9) + t];
    __syncthreads();
    int c = tid & 63;
    int mi = tid >> 6;
    if (c < 54) {
        float a0 = 0.f, a1 = 0.f, a2 = 0.f, a3 = 0.f;
#pragma unroll 4
        for (int k = 0; k < 512; k++) {
            float w = g_hwT[(size_t)k * 54 + c];
            a0 += sf[mi + 0][k] * w;
            a1 += sf[mi + 4][k] * w;
            a2 += sf[mi + 8][k] * w;
            a3 += sf[mi + 12][k] * w;
        }
        write_head(out, m0 + mi + 0, c, a0, loc_b, score_b);
        write_head(out, m0 + mi + 4, c, a1, loc_b, score_b);
        write_head(out, m0 + mi + 8, c, a2, loc_b, score_b);
        write_head(out, m0 + mi + 12, c, a3, loc_b, score_b);
    }
}

// ---------------- decode (fp32 only; anchor base from table) ----------------
__global__ void decode_kernel(float* out, const int* __restrict__ imh,
                              const int* __restrict__ imw) {
    int t = blockIdx.x * blockDim.x + threadIdx.x;
    if (t >= NBATCH * NA) return;
    int b = t / NA, i = t % NA;
    int pos = i / 9, a = i % 9;
    int y = pos / 50, x = pos % 50;

    float4 ab = *reinterpret_cast<const float4*>(g_abase[a]);
    float sx = (float)(x * 16), sy = (float)(y * 16);
    float ax1 = sx + ab.x, ay1 = sy + ab.y, ax2 = sx + ab.z, ay2 = sy + ab.w;

    if (b == 0) {
        float* ap = &out[(size_t)OFF_ANCH + (size_t)i * 4];
        ap[0] = ax1; ap[1] = ay1; ap[2] = ax2; ap[3] = ay2;
    }

    const float* lp = &out[(size_t)OFF_LOCS + ((size_t)b * NA + i) * 4];
    float l0 = lp[0], l1 = lp[1], l2 = lp[2], l3 = lp[3];
    const float* spt = &out[(size_t)OFF_SCORES + ((size_t)b * NA + i) * 2];
    float s0 = spt[0], s1 = spt[1];

    float aw = ax2 - ax1, ah = ay2 - ay1;
    float acx = ax1 + 0.5f * aw, acy = ay1 + 0.5f * ah;
    float cx = l0 * aw + acx, cy = l1 * ah + acy;
    float bw = expf(l2) * aw, bh = expf(l3) * ah;

    float Wf = (float)imw[0], Hf = (float)imh[0];
    float x1 = fminf(fmaxf(cx - 0.5f * bw, 0.f), Wf);
    float y1 = fminf(fmaxf(cy - 0.5f * bh, 0.f), Hf);
    float x2 = fminf(fmaxf(cx + 0.5f * bw, 0.f), Wf);
    float y2 = fminf(fmaxf(cy + 0.5f * bh, 0.f), Hf);

    bool valid = (x2 - x1 + 1.f >= 16.f) && (y2 - y1 + 1.f >= 16.f);

    float mx = fmaxf(s0, s1);
    float e0 = expf(s0 - mx), e1 = expf(s1 - mx);
    float fg = e1 / (e0 + e1);

    float* bp = &g_boxes[((size_t)b * NA + i) * 4];
    bp[0] = x1; bp[1] = y1; bp[2] = x2; bp[3] = y2;

    // 32-bit key: [2b batch][30b]. For fg in [0,1], ~flip(fg) has bits31:30==01.
    unsigned low30;
    if (valid) {
        unsigned u = __float_as_uint(fg);
        unsigned flip = (u & 0x80000000u) ? ~u : (u | 0x80000000u);
        low30 = (~flip) & 0x3FFFFFFFu;
    } else {
        low30 = 0x3FFFFFFFu;   // sorts after every valid score
    }
    g_keys32[(size_t)b * NA + i] = ((unsigned)b << 30) | low30;
    g_vals[(size_t)b * NA + i] = i;
}

// ---------------- gather top-3000 ----------------
__global__ void gather_kernel() {
    int t = blockIdx.x * blockDim.x + threadIdx.x;
    if (t >= NBATCH * NPRE) return;
    int b = t / NPRE, r = t % NPRE;
    unsigned key = g_keysOut32[(size_t)b * NA + r];
    int i = g_valsOut[(size_t)b * NA + r];
    float4 box = reinterpret_cast<const float4*>(g_boxes)[(size_t)b * NA + i];
    reinterpret_cast<float4*>(g_top)[(size_t)b * NPRE + r] = box;
    g_topValid[(size_t)b * NPRE + r] = ((key & 0x3FFFFFFFu) != 0x3FFFFFFFu) ? 1 : 0;
}

// ---------------- IoU bitmask matrix (division-free) ----------------
__global__ void __launch_bounds__(128) nms_mask_kernel() {
    __shared__ float4 sb[NPRE];
    int b = blockIdx.y;
    for (int t = threadIdx.x; t < NPRE; t += 128)
        sb[t] = reinterpret_cast<const float4*>(g_top)[(size_t)b * NPRE + t];
    __syncthreads();
    int i = blockIdx.x * 128 + threadIdx.x;
    if (i >= NPRE) return;
    float4 bi = sb[i];
    float ai = (bi.z - bi.x) * (bi.w - bi.y);
    unsigned* rowp = &g_nmsMask[((size_t)b * NPRE + i) * NWORDS];
    int jw0 = i >> 5;
    for (int jw = 0; jw < NWORDS; jw++) {
        unsigned bits = 0;
        if (jw >= jw0) {
            int jbase = jw * 32;
#pragma unroll 4
            for (int k = 0; k < 32; k++) {
                int j = jbase + k;
                if (j > i && j < NPRE) {
                    float4 bj = sb[j];
                    float iw = fmaxf(fminf(bi.z, bj.z) - fmaxf(bi.x, bj.x), 0.f);
                    float ih = fmaxf(fminf(bi.w, bj.w) - fmaxf(bi.y, bj.y), 0.f);
                    float inter = iw * ih;
                    float aj = (bj.z - bj.x) * (bj.w - bj.y);
                    if (inter > 0.7f * (ai + aj - inter + 1e-9f)) bits |= 1u << k;
                }
            }
        }
        rowp[jw] = bits;
    }
}

// ---------------- greedy scan: ffs skip over suppressed ----------------
__global__ void __launch_bounds__(32) nms_scan_kernel(float* out) {
    __shared__ unsigned sup[96];
    __shared__ unsigned vb[96];
    int b = blockIdx.x;
    int lane = threadIdx.x;

    for (int t = lane; t < NPOST * 4; t += 32)
        out[(size_t)OFF_ROIS + (size_t)b * NPOST * 4 + t] = 0.f;

#pragma unroll
    for (int q = 0; q < 3; q++) {
        int w = lane + 32 * q;
        sup[w] = 0;
        unsigned v = 0;
        if (w < NWORDS) {
            for (int k = 0; k < 32; k++) {
                int j = w * 32 + k;
                if (j < NPRE && g_topValid[(size_t)b * NPRE + j]) v |= 1u << k;
            }
        }
        vb[w] = v;
    }
    __syncwarp();

    const unsigned* maskBase = &g_nmsMask[(size_t)b * NPRE * NWORDS];
    int cnt = 0;
    int i = 0;
    while (cnt < NPOST) {
        int w = i >> 5;
        if (w >= NWORDS) break;
        unsigned live = (vb[w] & ~sup[w]) & (0xFFFFFFFFu << (i & 31));
        while (live == 0) {
            if (++w >= NWORDS) { w = -1; break; }
            live = vb[w] & ~sup[w];
        }
        if (w < 0) break;
        i = w * 32 + (__ffs(live) - 1);

        if (lane < 4)
            out[(size_t)OFF_ROIS + ((size_t)b * NPOST + cnt) * 4 + lane] =
                g_top[((size_t)b * NPRE + i) * 4 + lane];
        cnt++;

        const unsigned* row = maskBase + (size_t)i * NWORDS;
#pragma unroll
        for (int q = 0; q < 3; q++) {
            int ww = lane + 32 * q;
            if (ww < NWORDS) sup[ww] |= row[ww];
        }
        __syncwarp();
        i++;
    }
}

// ---------------- roi indices ----------------
__global__ void ridx_kernel(float* out) {
    int t = blockIdx.x * blockDim.x + threadIdx.x;
    if (t < NBATCH * NPOST) out[(size_t)OFF_RIDX + t] = (float)(t / NPOST);
}

// ---------------- launch ----------------
extern "C" void kernel_launch(void* const* d_in, const int* in_sizes, int n_in,
                              void* d_out, int out_size) {
    const float* x = (const float*)d_in[0];
    const float* conv1_w = (const float*)d_in[1];
    const float* conv1_b = (const float*)d_in[2];
    const float* loc_w = (const float*)d_in[3];
    const float* loc_b = (const float*)d_in[4];
    const float* score_w = (const float*)d_in[5];
    const float* score_b = (const float*)d_in[6];
    const int* img_h = (const int*)d_in[7];
    const int* img_w = (const int*)d_in[8];
    float* out = (float*)d_out;

    wtrans_kernel<<<(512 * 9 * 512 + 255) / 256, 256>>>(conv1_w);
    hwtrans_kernel<<<(512 * 54 + 255) / 256, 256>>>(loc_w, score_w);
    anchor_init<<<1, 32>>>();

    cudaFuncSetAttribute(conv3x3_v5, cudaFuncAttributeMaxDynamicSharedMemorySize,
                         CONV_SMEM);
    conv3x3_v5<<<dim3(40, 2, NBATCH), 256, CONV_SMEM>>>(x, conv1_b);

    heads_kernel<<<625, 256>>>(loc_b, score_b, out);

    decode_kernel<<<(NBATCH * NA + 255) / 256, 256>>>(out, img_h, img_w);

    // single full-device stable radix sort over 32-bit [2b batch | 30b score]
    void *pKeys, *pKeysOut, *pVals, *pValsOut, *pTemp;
    cudaGetSymbolAddress(&pKeys, g_keys32);
    cudaGetSymbolAddress(&pKeysOut, g_keysOut32);
    cudaGetSymbolAddress(&pVals, g_vals);
    cudaGetSymbolAddress(&pValsOut, g_valsOut);
    cudaGetSymbolAddress(&pTemp, g_cubTemp);

    size_t temp_bytes = 0;
    cub::DeviceRadixSort::SortPairs(
        nullptr, temp_bytes,
        (const unsigned*)pKeys, (unsigned*)pKeysOut,
        (const int*)pVals, (int*)pValsOut, NBATCH * NA, 0, 32, (cudaStream_t)0);
    if (temp_bytes <= (size_t)(16 << 20)) {
        cub::DeviceRadixSort::SortPairs(
            pTemp, temp_bytes,
            (const unsigned*)pKeys, (unsigned*)pKeysOut,
            (const int*)pVals, (int*)pValsOut, NBATCH * NA, 0, 32, (cudaStream_t)0);
    }

    gather_kernel<<<(NBATCH * NPRE + 255) / 256, 256>>>();
    nms_mask_kernel<<<dim3((NPRE + 127) / 128, NBATCH), 128>>>();
    nms_scan_kernel<<<NBATCH, 32>>>(out);
    ridx_kernel<<<(NBATCH * NPOST + 255) / 256, 256>>>(out);
}

// round 11
// speedup vs baseline: 1.4951x; 1.4951x over previous
#include <cuda_runtime.h>
#include <cub/cub.cuh>
#include <cstdint>
#include <math.h>

// ---------------- problem constants ----------------
#define NBATCH 4
#define FH 50
#define FW 50
#define NA 22500          // anchors per batch (50*50*9)
#define NPRE 3000
#define NPOST 300
#define NWORDS 94         // ceil(3000/32)

// output layout (flattened tuple, float32)
#define OFF_LOCS   0            // 4*22500*4 = 360000
#define OFF_SCORES 360000       // 4*22500*2 = 180000
#define OFF_ROIS   540000       // 4*300*4   = 4800
#define OFF_RIDX   544800       // 1200
#define OFF_ANCH   546000       // 22500*4   = 90000

// ---------------- device scratch ----------------
__device__ float g_feat[(size_t)NBATCH * 2500 * 512];   // NHWC feat
__device__ float g_wT[(size_t)512 * 9 * 512];            // [ci][tap][ko]
__device__ float g_hwT[(size_t)512 * 54];                // [k][c]
__device__ float g_boxes[(size_t)NBATCH * NA * 4];
__device__ unsigned g_keys32[(size_t)NBATCH * NA];
__device__ unsigned g_keysOut32[(size_t)NBATCH * NA];
__device__ int g_vals[(size_t)NBATCH * NA];
__device__ int g_valsOut[(size_t)NBATCH * NA];
__device__ float g_top[(size_t)NBATCH * NPRE * 4];
__device__ unsigned char g_topValid[(size_t)NBATCH * NPRE];
__device__ unsigned g_nmsMask[(size_t)NBATCH * NPRE * NWORDS];
__device__ float g_abase[9][4];
__device__ unsigned char g_cubTemp[16 << 20];

// packed fp32x2 FMA: d.lo = a.lo*b.lo+d.lo ; d.hi = a.hi*b.hi+d.hi (exact fp32)
#define FMA2(d, a, w) \
    asm("fma.rn.f32x2 %0, %1, %2, %3;" : "=l"(d) : "l"(a), "l"(w), "l"(d))

// ---------------- anchor base table (double math, once) ----------------
__global__ void anchor_init() {
    int a = threadIdx.x;
    if (a >= 9) return;
    int ri = a / 3, si = a % 3;
    double rr = (ri == 0) ? 0.5 : ((ri == 1) ? 1.0 : 2.0);
    double ss = (si == 0) ? 8.0 : ((si == 1) ? 16.0 : 32.0);
    double hh = 16.0 * ss * sqrt(rr);
    double wwd = 16.0 * ss * sqrt(1.0 / rr);
    g_abase[a][0] = (float)(8.0 - wwd * 0.5);
    g_abase[a][1] = (float)(8.0 - hh * 0.5);
    g_abase[a][2] = (float)(8.0 + wwd * 0.5);
    g_abase[a][3] = (float)(8.0 + hh * 0.5);
}

// ---------------- weight transposes ----------------
__global__ void wtrans_kernel(const float* __restrict__ w) {
    int t = blockIdx.x * blockDim.x + threadIdx.x;
    if (t >= 512 * 9 * 512) return;
    int ko = t % 512;
    int tap = (t / 512) % 9;
    int ci = t / (512 * 9);
    g_wT[t] = w[((size_t)ko * 512 + ci) * 9 + tap];
}

__global__ void hwtrans_kernel(const float* __restrict__ loc_w,
                               const float* __restrict__ score_w) {
    int t = blockIdx.x * blockDim.x + threadIdx.x;
    if (t >= 512 * 54) return;
    int k = t / 54, c = t % 54;
    float v;
    if (c < 36) v = loc_w[(size_t)c * 512 + k];
    else        v = score_w[(size_t)(c - 36) * 512 + k];
    g_hwT[t] = v;
}

// ---------------- 3x3 conv + ReLU, f32x2 implicit GEMM v6 ----------------
// v4 tiling (72 spatial x 256 ko, grid 35x2x4 = 280 = one full wave @2 CTA/SM),
// v4 FMA2 compute loop, but staging loops have ZERO per-iteration index math:
// input halo offsets hoisted to prologue registers, weight loop is constant-
// stride (ptxas emits LDG/STS with immediate offsets).
#define CONV_SIN   (8 * 5 * 52)                      // dup pairs: 2080
#define CONV_SW    (8 * 9 * 256)                     // 18432 floats
#define CONV_SMEM  (CONV_SIN * 8 + CONV_SW * 4)      // 90368 B

__global__ void __launch_bounds__(256, 2) conv3x3_v6(const float* __restrict__ x,
                                                     const float* __restrict__ bias) {
    extern __shared__ unsigned char smraw[];
    float2* sIn2 = reinterpret_cast<float2*>(smraw);            // dup pairs
    float* sW = reinterpret_cast<float*>(smraw + CONV_SIN * 8);

    int mt = blockIdx.x;             // 0..34
    int nt = blockIdx.y;             // 0..1
    int n = blockIdx.z;              // 0..3
    int s0 = mt * 72;
    int y0 = s0 / 50;
    int ko0 = nt * 256;
    int tid = threadIdx.x;
    int wid = tid >> 5, lane = tid & 31;

    // ---- compute-side spatial offsets (per warp) ----
    int off[9];
#pragma unroll
    for (int j = 0; j < 9; j++) {
        int s = s0 + wid * 9 + j;
        int sc = s < 2499 ? s : 2499;
        int yy = sc / 50, xx = sc % 50;
        off[j] = (yy - y0 + 1) * 52 + xx + 1;
    }

    // ---- input staging descriptors, computed ONCE ----
    // slot j covers tile element t = tid + j*256 (t < 2080).
    // iofs[j] = offset into x (for ci/channel 0 of the chunk) or -1 if halo-OOB.
    const float* xn = x + (size_t)n * 512 * 2500;
    int iofs[9];
#pragma unroll
    for (int j = 0; j < 9; j++) {
        int t = tid + j * 256;
        int ci = t / 260;
        int rem = t % 260;
        int r = rem / 52;
        int cc = rem % 52;
        int gy = y0 - 1 + r;
        int gx = cc - 1;
        bool ok = (t < CONV_SIN) && gy >= 0 && gy < FH && gx >= 0 && gx < FW;
        iofs[j] = ok ? (ci * 2500 + gy * 50 + gx) : -1;
    }
    bool has9 = (tid < CONV_SIN - 8 * 256);   // slot 8 in range?

    unsigned long long acc[9][4];
#pragma unroll
    for (int j = 0; j < 9; j++)
#pragma unroll
        for (int k = 0; k < 4; k++) acc[j][k] = 0ull;

    const unsigned long long* aBase =
        reinterpret_cast<const unsigned long long*>(sIn2);

    int koLane = tid & 255;   // for weight staging
    int rest0 = tid >> 8;     // 0 (all threads; 256 threads -> rest0 = 0)

    for (int c0 = 0; c0 < 512; c0 += 8) {
        __syncthreads();
        // ---- input tile: 1 LDG + 1 STS per slot, no index math ----
        const float* xc = xn + (size_t)c0 * 2500;
#pragma unroll
        for (int j = 0; j < 9; j++) {
            int o = iofs[j];
            float v = (o >= 0) ? xc[o] : 0.f;
            if (j < 8 || has9) sIn2[tid + j * 256] = make_float2(v, v);
        }
        // ---- weights: constant-stride copy, 72 slots, stride 256 threads ----
        {
            const float* gw = g_wT + ((size_t)c0 * 9 + rest0) * 512 + ko0 + koLane;
            float* sw = sW + tid;
#pragma unroll 8
            for (int k = 0; k < 72; k++)
                sw[(size_t)k * 256] = gw[(size_t)k * 512];
        }
        __syncthreads();

#pragma unroll 1
        for (int ci = 0; ci < 8; ci++) {
            const unsigned long long* aci = aBase + ci * 260;
            const float* wci = sW + ci * 9 * 256 + 8 * lane;
#pragma unroll
            for (int dy = 0; dy < 3; dy++) {
#pragma unroll
                for (int dx = 0; dx < 3; dx++) {
                    int tap = dy * 3 + dx;
                    ulonglong2 wA = *reinterpret_cast<const ulonglong2*>(wci + tap * 256);
                    ulonglong2 wB = *reinterpret_cast<const ulonglong2*>(wci + tap * 256 + 4);
                    int d = (dy - 1) * 52 + (dx - 1);
#pragma unroll
                    for (int j = 0; j < 9; j++) {
                        unsigned long long av = aci[off[j] + d];
                        FMA2(acc[j][0], av, wA.x);
                        FMA2(acc[j][1], av, wA.y);
                        FMA2(acc[j][2], av, wB.x);
                        FMA2(acc[j][3], av, wB.y);
                    }
                }
            }
        }
    }

    // epilogue: + bias, ReLU, store NHWC (8 consecutive ko per thread @ lane*8)
    int koL = 8 * lane;
    float4 b0 = *reinterpret_cast<const float4*>(&bias[ko0 + koL]);
    float4 b1 = *reinterpret_cast<const float4*>(&bias[ko0 + koL + 4]);
#pragma unroll
    for (int j = 0; j < 9; j++) {
        int s = s0 + wid * 9 + j;
        if (s < 2500) {
            float2 p0 = *reinterpret_cast<float2*>(&acc[j][0]);
            float2 p1 = *reinterpret_cast<float2*>(&acc[j][1]);
            float2 p2 = *reinterpret_cast<float2*>(&acc[j][2]);
            float2 p3 = *reinterpret_cast<float2*>(&acc[j][3]);
            float4 v0, v1;
            v0.x = fmaxf(p0.x + b0.x, 0.f);
            v0.y = fmaxf(p0.y + b0.y, 0.f);
            v0.z = fmaxf(p1.x + b0.z, 0.f);
            v0.w = fmaxf(p1.y + b0.w, 0.f);
            v1.x = fmaxf(p2.x + b1.x, 0.f);
            v1.y = fmaxf(p2.y + b1.y, 0.f);
            v1.z = fmaxf(p3.x + b1.z, 0.f);
            v1.w = fmaxf(p3.y + b1.w, 0.f);
            float* op = &g_feat[((size_t)n * 2500 + s) * 512 + ko0 + koL];
            *reinterpret_cast<float4*>(op) = v0;
            *reinterpret_cast<float4*>(op + 4) = v1;
        }
    }
}

// ---------------- 1x1 heads (loc 36 + score 18) ----------------
__device__ __forceinline__ void write_head(float* out, int m, int c, float acc,
                                           const float* __restrict__ loc_b,
                                           const float* __restrict__ score_b) {
    int n = m / 2500, pos = m % 2500;
    if (c < 36) {
        int a = c >> 2, j = c & 3;
        out[(size_t)OFF_LOCS + ((size_t)n * NA + (size_t)pos * 9 + a) * 4 + j] = acc + loc_b[c];
    } else {
        int cc = c - 36;
        int a = cc >> 1, j = cc & 1;
        out[(size_t)OFF_SCORES + ((size_t)n * NA + (size_t)pos * 9 + a) * 2 + j] = acc + score_b[cc];
    }
}

__global__ void __launch_bounds__(256) heads_kernel(const float* __restrict__ loc_b,
                                                    const float* __restrict__ score_b,
                                                    float* out) {
    __shared__ float sf[16][512];
    int m0 = blockIdx.x * 16;
    int tid = threadIdx.x;
    for (int t = tid; t < 16 * 512; t += 256)
        sf[t >> 9][t & 511] = g_feat[((size_t)m0 << 9) + t];
    __syncthreads();
    int c = tid & 63;
    int mi = tid >> 6;
    if (c < 54) {
        float a0 = 0.f, a1 = 0.f, a2 = 0.f, a3 = 0.f;
#pragma unroll 4
        for (int k = 0; k < 512; k++) {
            float w = g_hwT[(size_t)k * 54 + c];
            a0 += sf[mi + 0][k] * w;
            a1 += sf[mi + 4][k] * w;
            a2 += sf[mi + 8][k] * w;
            a3 += sf[mi + 12][k] * w;
        }
        write_head(out, m0 + mi + 0, c, a0, loc_b, score_b);
        write_head(out, m0 + mi + 4, c, a1, loc_b, score_b);
        write_head(out, m0 + mi + 8, c, a2, loc_b, score_b);
        write_head(out, m0 + mi + 12, c, a3, loc_b, score_b);
    }
}

// ---------------- decode (fp32 only; anchor base from table) ----------------
__global__ void decode_kernel(float* out, const int* __restrict__ imh,
                              const int* __restrict__ imw) {
    int t = blockIdx.x * blockDim.x + threadIdx.x;
    if (t >= NBATCH * NA) return;
    int b = t / NA, i = t % NA;
    int pos = i / 9, a = i % 9;
    int y = pos / 50, x = pos % 50;

    float4 ab = *reinterpret_cast<const float4*>(g_abase[a]);
    float sx = (float)(x * 16), sy = (float)(y * 16);
    float ax1 = sx + ab.x, ay1 = sy + ab.y, ax2 = sx + ab.z, ay2 = sy + ab.w;

    if (b == 0) {
        float* ap = &out[(size_t)OFF_ANCH + (size_t)i * 4];
        ap[0] = ax1; ap[1] = ay1; ap[2] = ax2; ap[3] = ay2;
    }

    const float* lp = &out[(size_t)OFF_LOCS + ((size_t)b * NA + i) * 4];
    float l0 = lp[0], l1 = lp[1], l2 = lp[2], l3 = lp[3];
    const float* spt = &out[(size_t)OFF_SCORES + ((size_t)b * NA + i) * 2];
    float s0 = spt[0], s1 = spt[1];

    float aw = ax2 - ax1, ah = ay2 - ay1;
    float acx = ax1 + 0.5f * aw, acy = ay1 + 0.5f * ah;
    float cx = l0 * aw + acx, cy = l1 * ah + acy;
    float bw = expf(l2) * aw, bh = expf(l3) * ah;

    float Wf = (float)imw[0], Hf = (float)imh[0];
    float x1 = fminf(fmaxf(cx - 0.5f * bw, 0.f), Wf);
    float y1 = fminf(fmaxf(cy - 0.5f * bh, 0.f), Hf);
    float x2 = fminf(fmaxf(cx + 0.5f * bw, 0.f), Wf);
    float y2 = fminf(fmaxf(cy + 0.5f * bh, 0.f), Hf);

    bool valid = (x2 - x1 + 1.f >= 16.f) && (y2 - y1 + 1.f >= 16.f);

    float mx = fmaxf(s0, s1);
    float e0 = expf(s0 - mx), e1 = expf(s1 - mx);
    float fg = e1 / (e0 + e1);

    float* bp = &g_boxes[((size_t)b * NA + i) * 4];
    bp[0] = x1; bp[1] = y1; bp[2] = x2; bp[3] = y2;

    // 32-bit key: [2b batch][30b]. For fg in [0,1], ~flip(fg) has bits31:30==01.
    unsigned low30;
    if (valid) {
        unsigned u = __float_as_uint(fg);
        unsigned flip = (u & 0x80000000u) ? ~u : (u | 0x80000000u);
        low30 = (~flip) & 0x3FFFFFFFu;
    } else {
        low30 = 0x3FFFFFFFu;   // sorts after every valid score
    }
    g_keys32[(size_t)b * NA + i] = ((unsigned)b << 30) | low30;
    g_vals[(size_t)b * NA + i] = i;
}

// ---------------- gather top-3000 ----------------
__global__ void gather_kernel() {
    int t = blockIdx.x * blockDim.x + threadIdx.x;
    if (t >= NBATCH * NPRE) return;
    int b = t / NPRE, r = t % NPRE;
    unsigned key = g_keysOut32[(size_t)b * NA + r];
    int i = g_valsOut[(size_t)b * NA + r];
    float4 box = reinterpret_cast<const float4*>(g_boxes)[(size_t)b * NA + i];
    reinterpret_cast<float4*>(g_top)[(size_t)b * NPRE + r] = box;
    g_topValid[(size_t)b * NPRE + r] = ((key & 0x3FFFFFFFu) != 0x3FFFFFFFu) ? 1 : 0;
}

// ---------------- IoU bitmask matrix (division-free, split j-halves) -------
#define NMS_JSPLIT 2
#define NMS_JW     ((NWORDS + NMS_JSPLIT - 1) / NMS_JSPLIT)   // 47
__global__ void __launch_bounds__(128) nms_mask_kernel() {
    __shared__ float4 sb[NPRE];
    int b = blockIdx.z;
    int jh = blockIdx.y;
    for (int t = threadIdx.x; t < NPRE; t += 128)
        sb[t] = reinterpret_cast<const float4*>(g_top)[(size_t)b * NPRE + t];
    __syncthreads();
    int i = blockIdx.x * 128 + threadIdx.x;
    if (i >= NPRE) return;
    float4 bi = sb[i];
    float ai = (bi.z - bi.x) * (bi.w - bi.y);
    unsigned* rowp = &g_nmsMask[((size_t)b * NPRE + i) * NWORDS];
    int jw0 = i >> 5;
    int jbeg = jh * NMS_JW;
    int jend = min(jbeg + NMS_JW, NWORDS);
    for (int jw = jbeg; jw < jend; jw++) {
        unsigned bits = 0;
        if (jw >= jw0) {
            int jbase = jw * 32;
#pragma unroll 4
            for (int k = 0; k < 32; k++) {
                int j = jbase + k;
                if (j > i && j < NPRE) {
                    float4 bj = sb[j];
                    float iw = fmaxf(fminf(bi.z, bj.z) - fmaxf(bi.x, bj.x), 0.f);
                    float ih = fmaxf(fminf(bi.w, bj.w) - fmaxf(bi.y, bj.y), 0.f);
                    float inter = iw * ih;
                    float aj = (bj.z - bj.x) * (bj.w - bj.y);
                    if (inter > 0.7f * (ai + aj - inter + 1e-9f)) bits |= 1u << k;
                }
            }
        }
        rowp[jw] = bits;
    }
}

// ---------------- greedy scan: ffs skip over suppressed ----------------
__global__ void __launch_bounds__(32) nms_scan_kernel(float* out) {
    __shared__ unsigned sup[96];
    __shared__ unsigned vb[96];
    int b = blockIdx.x;
    int lane = threadIdx.x;

    for (int t = lane; t < NPOST * 4; t += 32)
        out[(size_t)OFF_ROIS + (size_t)b * NPOST * 4 + t] = 0.f;

#pragma unroll
    for (int q = 0; q < 3; q++) {
        int w = lane + 32 * q;
        sup[w] = 0;
        unsigned v = 0;
        if (w < NWORDS) {
            for (int k = 0; k < 32; k++) {
                int j = w * 32 + k;
                if (j < NPRE && g_topValid[(size_t)b * NPRE + j]) v |= 1u << k;
            }
        }
        vb[w] = v;
    }
    __syncwarp();

    const unsigned* maskBase = &g_nmsMask[(size_t)b * NPRE * NWORDS];
    int cnt = 0;
    int i = 0;
    while (cnt < NPOST) {
        int w = i >> 5;
        if (w >= NWORDS) break;
        unsigned live = (vb[w] & ~sup[w]) & (0xFFFFFFFFu << (i & 31));
        while (live == 0) {
            if (++w >= NWORDS) { w = -1; break; }
            live = vb[w] & ~sup[w];
        }
        if (w < 0) break;
        i = w * 32 + (__ffs(live) - 1);

        if (lane < 4)
            out[(size_t)OFF_ROIS + ((size_t)b * NPOST + cnt) * 4 + lane] =
                g_top[((size_t)b * NPRE + i) * 4 + lane];
        cnt++;

        const unsigned* row = maskBase + (size_t)i * NWORDS;
#pragma unroll
        for (int q = 0; q < 3; q++) {
            int ww = lane + 32 * q;
            if (ww < NWORDS) sup[ww] |= row[ww];
        }
        __syncwarp();
        i++;
    }
}

// ---------------- roi indices ----------------
__global__ void ridx_kernel(float* out) {
    int t = blockIdx.x * blockDim.x + threadIdx.x;
    if (t < NBATCH * NPOST) out[(size_t)OFF_RIDX + t] = (float)(t / NPOST);
}

// ---------------- launch ----------------
extern "C" void kernel_launch(void* const* d_in, const int* in_sizes, int n_in,
                              void* d_out, int out_size) {
    const float* x = (const float*)d_in[0];
    const float* conv1_w = (const float*)d_in[1];
    const float* conv1_b = (const float*)d_in[2];
    const float* loc_w = (const float*)d_in[3];
    const float* loc_b = (const float*)d_in[4];
    const float* score_w = (const float*)d_in[5];
    const float* score_b = (const float*)d_in[6];
    const int* img_h = (const int*)d_in[7];
    const int* img_w = (const int*)d_in[8];
    float* out = (float*)d_out;

    wtrans_kernel<<<(512 * 9 * 512 + 255) / 256, 256>>>(conv1_w);
    hwtrans_kernel<<<(512 * 54 + 255) / 256, 256>>>(loc_w, score_w);
    anchor_init<<<1, 32>>>();

    cudaFuncSetAttribute(conv3x3_v6, cudaFuncAttributeMaxDynamicSharedMemorySize,
                         CONV_SMEM);
    conv3x3_v6<<<dim3(35, 2, NBATCH), 256, CONV_SMEM>>>(x, conv1_b);

    heads_kernel<<<625, 256>>>(loc_b, score_b, out);

    decode_kernel<<<(NBATCH * NA + 255) / 256, 256>>>(out, img_h, img_w);

    // single full-device stable radix sort over 32-bit [2b batch | 30b score]
    void *pKeys, *pKeysOut, *pVals, *pValsOut, *pTemp;
    cudaGetSymbolAddress(&pKeys, g_keys32);
    cudaGetSymbolAddress(&pKeysOut, g_keysOut32);
    cudaGetSymbolAddress(&pVals, g_vals);
    cudaGetSymbolAddress(&pValsOut, g_valsOut);
    cudaGetSymbolAddress(&pTemp, g_cubTemp);

    size_t temp_bytes = 0;
    cub::DeviceRadixSort::SortPairs(
        nullptr, temp_bytes,
        (const unsigned*)pKeys, (unsigned*)pKeysOut,
        (const int*)pVals, (int*)pValsOut, NBATCH * NA, 0, 32, (cudaStream_t)0);
    if (temp_bytes <= (size_t)(16 << 20)) {
        cub::DeviceRadixSort::SortPairs(
            pTemp, temp_bytes,
            (const unsigned*)pKeys, (unsigned*)pKeysOut,
            (const int*)pVals, (int*)pValsOut, NBATCH * NA, 0, 32, (cudaStream_t)0);
    }

    gather_kernel<<<(NBATCH * NPRE + 255) / 256, 256>>>();
    nms_mask_kernel<<<dim3((NPRE + 127) / 128, NMS_JSPLIT, NBATCH), 128>>>();
    nms_scan_kernel<<<NBATCH, 32>>>(out);
    ridx_kernel<<<(NBATCH * NPOST + 255) / 256, 256>>>(out);
}